// round 5
// baseline (speedup 1.0000x reference)
#include <cuda_runtime.h>

// Problem constants (SLEN=208, PTILE=8, STEP=2, EDGE=3, MAXDET=2)
#define BATCH 16
#define NSRC  100
#define NFLUX 5
#define NT    101                 // tiles per dim
#define PT    (NT * NT)           // 10201
#define BP    (BATCH * PT)        // 163216
// Output sections (float32, concatenated):
//   n [BP] | locs [BP*4] | fluxes [BP*10] | is_on [BP*2]
#define OFF_L (BP)                 // 163216  (mult of 4)
#define OFF_F (OFF_L + BP * 4)     // 816080  (mult of 4)
#define OFF_I (OFF_F + BP * 10)    // 2448240 (mult of 4)

#define TPB    256
#define CHUNK  136                         // mult of 4, < PT (spans <= 2 batches)
#define GRID   ((BP + CHUNK - 1) / CHUNK)  // 1201 (last block: 16 cells)
#define MAXLOC 256

// Map pixel coords -> (tile, fx, fy); returns tile or -1. Bit-identical to R1.
__device__ __forceinline__ int map_source(float l0, float l1, float& fx, float& fy) {
    float p0 = l0 * 207.0f;                                  // SLEN-1
    float p1 = l1 * 207.0f;
    int kx = (int)floorf((p0 - 2.5f) * 0.5f);
    int ky = (int)floorf((p1 - 2.5f) * 0.5f);
    float lx = 2.0f * (float)kx + 2.5f;                      // exact fp32
    float ly = 2.0f * (float)ky + 2.5f;
    bool v0 = (kx >= 0) && (kx < NT) && (p0 > lx) && (p0 < lx + 2.0f) && (p0 != 0.0f);
    bool v1 = (ky >= 0) && (ky < NT) && (p1 > ly) && (p1 < ly + 2.0f) && (p1 != 0.0f);
    if (!(v0 && v1)) return -1;
    fx = (p0 - lx) * 0.5f;                                   // (lp - left)/scale, exact
    fy = (p1 - ly) * 0.5f;
    return kx * NT + ky;
}

__global__ __launch_bounds__(TPB)
void fused_kernel(const float* __restrict__ locs,
                  const float* __restrict__ fluxes,
                  float* __restrict__ out) {
    __shared__ int   s_cnt;
    __shared__ int   s_ent[MAXLOC];   // (g << 11) | idx
    __shared__ float s_fx[MAXLOC];
    __shared__ float s_fy[MAXLOC];

    const int t  = threadIdx.x;
    const int g0 = blockIdx.x * CHUNK;
    const int g1 = min(g0 + CHUNK, BP);
    const int n  = g1 - g0;           // always a multiple of 4

    if (t == 0) s_cnt = 0;

    // ---- Phase A: zero the 4 per-section slices. All bases 16B-aligned,
    //      all counts exact float4 multiples -> 5 predicated STG.128 total.
    {
        const float4 z = make_float4(0.f, 0.f, 0.f, 0.f);
        float4* __restrict__ pN = (float4*)(out + g0);            // n/4   <= 34
        float4* __restrict__ pL = (float4*)(out + OFF_L + 4  * g0); // n     <= 136
        float4* __restrict__ pF = (float4*)(out + OFF_F + 10 * g0); // 10n/4 <= 340
        float4* __restrict__ pI = (float4*)(out + OFF_I + 2  * g0); // n/2   <= 68
        const int cF = (10 * n) >> 2;
        if (t < (n >> 2))   pN[t] = z;
        if (t < n)          pL[t] = z;
        if (t < cF)         pF[t] = z;
        if (t + TPB < cF)   pF[t + TPB] = z;
        if (t < (n >> 1))   pI[t] = z;
    }
    __syncthreads();   // s_cnt init visible; (Phase-A stores ordered later too)

    // ---- Phase B: only the <=2 batches overlapping my cell range matter ----
    const int b_lo = g0 / PT;
    const int b_hi = (g1 - 1) / PT;
    const int i_lo = b_lo * NSRC;
    const int i_hi = (b_hi + 1) * NSRC;       // <= i_lo + 200

    const float2* __restrict__ l2 = (const float2*)locs;
    for (int idx = i_lo + t; idx < i_hi; idx += TPB) {   // <= 1 trip
        float2 l = __ldg(&l2[idx]);
        float fx, fy;
        int tile = map_source(l.x, l.y, fx, fy);
        if (tile < 0) continue;
        int g = (idx / NSRC) * PT + tile;
        if (g >= g0 && g < g1) {
            int pos = atomicAdd(&s_cnt, 1);
            s_ent[pos] = (g << 11) | idx;
            s_fx[pos]  = fx;
            s_fy[pos]  = fy;
        }
    }
    __syncthreads();   // orders Phase-A stores before Phase-C stores (CTA scope)

    // ---- Phase C: rank within tiny local list (~1-3 entries), write payloads ----
    const int cnt = s_cnt;
    for (int e = t; e < cnt; e += TPB) {
        const int ent = s_ent[e];
        const int g   = ent >> 11;
        const int idx = ent & 2047;

        int count = 0, rank = 0;
        for (int j = 0; j < cnt; j++) {
            int o = s_ent[j];
            if ((o >> 11) == g) {
                count++;
                if ((o & 2047) < idx) rank++;
            }
        }

        if (rank == 0)
            out[g] = (float)(count < 2 ? count : 2);     // min(n, MAXDET)

        if (rank < 2) {
            *(float2*)(out + OFF_L + 4 * g + 2 * rank) = make_float2(s_fx[e], s_fy[e]);

            const float* __restrict__ fl = fluxes + idx * NFLUX;
            int fb = OFF_F + 10 * g + 5 * rank;
            #pragma unroll
            for (int j = 0; j < NFLUX; j++) out[fb + j] = __ldg(&fl[j]);

            out[OFF_I + 2 * g + rank] = 1.0f;
        }
    }
}

extern "C" void kernel_launch(void* const* d_in, const int* in_sizes, int n_in,
                              void* d_out, int out_size) {
    const float* locs   = (const float*)d_in[0];   // (16, 100, 2) f32
    const float* fluxes = (const float*)d_in[1];   // (16, 100, 5) f32
    fused_kernel<<<GRID, TPB>>>(locs, fluxes, (float*)d_out);
}

// round 6
// speedup vs baseline: 1.3478x; 1.3478x over previous
#include <cuda_runtime.h>

// Problem constants (SLEN=208, PTILE=8, STEP=2, EDGE=3, MAXDET=2)
#define BATCH 16
#define NSRC  100
#define NFLUX 5
#define NT    101                 // tiles per dim
#define PT    (NT * NT)           // 10201
#define BP    (BATCH * PT)        // 163216
// Output sections (float32, concatenated):
//   n [BP] | locs [BP*4] | fluxes [BP*10] | is_on [BP*2]
#define OFF_L (BP)                 // 163216  (mult of 4)
#define OFF_F (OFF_L + BP * 4)     // 816080  (mult of 4)
#define OFF_I (OFF_F + BP * 10)    // 2448240 (mult of 4)

#define TPB    256
#define CHUNK  276                         // mult of 4, < PT (spans <= 2 batches)
#define GRID   ((BP + CHUNK - 1) / CHUNK)  // 592 = 4 blocks/SM, single wave
#define MAXLOC 256

// Map pixel coords -> (tile, fx, fy); returns tile or -1. Bit-identical to R1.
__device__ __forceinline__ int map_source(float l0, float l1, float& fx, float& fy) {
    float p0 = l0 * 207.0f;                                  // SLEN-1
    float p1 = l1 * 207.0f;
    int kx = (int)floorf((p0 - 2.5f) * 0.5f);
    int ky = (int)floorf((p1 - 2.5f) * 0.5f);
    float lx = 2.0f * (float)kx + 2.5f;                      // exact fp32
    float ly = 2.0f * (float)ky + 2.5f;
    bool v0 = (kx >= 0) && (kx < NT) && (p0 > lx) && (p0 < lx + 2.0f) && (p0 != 0.0f);
    bool v1 = (ky >= 0) && (ky < NT) && (p1 > ly) && (p1 < ly + 2.0f) && (p1 != 0.0f);
    if (!(v0 && v1)) return -1;
    fx = (p0 - lx) * 0.5f;                                   // (lp - left)/scale, exact
    fy = (p1 - ly) * 0.5f;
    return kx * NT + ky;
}

__global__ __launch_bounds__(TPB)
void fused_kernel(const float* __restrict__ locs,
                  const float* __restrict__ fluxes,
                  float* __restrict__ out) {
    __shared__ int   s_cnt;
    __shared__ int   s_ent[MAXLOC];   // (g << 11) | idx
    __shared__ float s_fx[MAXLOC];
    __shared__ float s_fy[MAXLOC];

    const int t  = threadIdx.x;
    const int g0 = blockIdx.x * CHUNK;
    const int g1 = min(g0 + CHUNK, BP);
    const int n  = g1 - g0;           // multiple of 4

    // ---- Issue the source load FIRST so its L2 latency overlaps the fill ----
    const int b_lo  = g0 / PT;
    const int b_hi  = (g1 - 1) / PT;          // <= b_lo + 1 (CHUNK < PT)
    const int i_lo  = b_lo * NSRC;
    const int span  = (b_hi + 1) * NSRC - i_lo;   // <= 200 <= TPB: no loop
    const int idx   = i_lo + t;
    const bool has  = (t < span);
    float2 l = make_float2(0.f, 0.f);
    if (has) l = __ldg(&((const float2*)locs)[idx]);   // in flight during Phase A

    if (t == 0) s_cnt = 0;

    // ---- Phase A: zero the 4 per-section slices; 7 predicated STG.128 ----
    {
        const float4 z = make_float4(0.f, 0.f, 0.f, 0.f);
        float4* __restrict__ pN = (float4*)(out + g0);
        float4* __restrict__ pL = (float4*)(out + OFF_L + 4  * g0);
        float4* __restrict__ pF = (float4*)(out + OFF_F + 10 * g0);
        float4* __restrict__ pI = (float4*)(out + OFF_I + 2  * g0);
        const int cN = n >> 2;          // <= 69
        const int cL = n;               // <= 276
        const int cF = (10 * n) >> 2;   // <= 690
        const int cI = n >> 1;          // <= 138
        if (t           < cN) pN[t]           = z;
        if (t           < cL) pL[t]           = z;
        if (t + TPB     < cL) pL[t + TPB]     = z;
        if (t           < cF) pF[t]           = z;
        if (t + TPB     < cF) pF[t + TPB]     = z;
        if (t + 2 * TPB < cF) pF[t + 2 * TPB] = z;
        if (t           < cI) pI[t]           = z;
    }
    __syncthreads();   // s_cnt=0 visible before atomics

    // ---- Phase B: classify my (already-loaded) source ----
    if (has) {
        float fx, fy;
        int tile = map_source(l.x, l.y, fx, fy);
        if (tile >= 0) {
            int g = (idx / NSRC) * PT + tile;
            if (g >= g0 && g < g1) {
                int pos = atomicAdd(&s_cnt, 1);
                s_ent[pos] = (g << 11) | idx;
                s_fx[pos]  = fx;
                s_fy[pos]  = fy;
            }
        }
    }
    __syncthreads();   // orders Phase-A stores before Phase-C stores (CTA scope)

    // ---- Phase C: rank within tiny local list (~1-5 entries), write payloads ----
    const int cnt = s_cnt;
    if (t < cnt) {
        const int ent = s_ent[t];
        const int g   = ent >> 11;
        const int sidx= ent & 2047;

        int count = 0, rank = 0;
        for (int j = 0; j < cnt; j++) {
            int o = s_ent[j];
            if ((o >> 11) == g) {
                count++;
                if ((o & 2047) < sidx) rank++;
            }
        }

        if (rank == 0)
            out[g] = (float)(count < 2 ? count : 2);     // min(n, MAXDET)

        if (rank < 2) {
            *(float2*)(out + OFF_L + 4 * g + 2 * rank) = make_float2(s_fx[t], s_fy[t]);

            const float* __restrict__ fl = fluxes + sidx * NFLUX;
            int fb = OFF_F + 10 * g + 5 * rank;
            #pragma unroll
            for (int j = 0; j < NFLUX; j++) out[fb + j] = __ldg(&fl[j]);

            out[OFF_I + 2 * g + rank] = 1.0f;
        }
    }
}

extern "C" void kernel_launch(void* const* d_in, const int* in_sizes, int n_in,
                              void* d_out, int out_size) {
    const float* locs   = (const float*)d_in[0];   // (16, 100, 2) f32
    const float* fluxes = (const float*)d_in[1];   // (16, 100, 5) f32
    fused_kernel<<<GRID, TPB>>>(locs, fluxes, (float*)d_out);
}